// round 9
// baseline (speedup 1.0000x reference)
#include <cuda_runtime.h>
#include <stdint.h>

// -----------------------------------------------------------------------------
// Polynomial edge-energy + segment sum. (indices are int32)
//   per edge e: x = |pos[m0]-pos[m1]|, V = v0[t0,t1] + sum_p ks[p,t0,t1]*x^(p+1)
//   y[g] = segment sum over sorted mapping_batch
// Strategy: L1tex gather-tag bound (~1 cyc/line/SM). Maximize tag-unit
// utilization: dynamic tile scheduling (no CTA-spread tail), per-thread
// register segment accumulator (no warp shuffles in hot loop), 8-gather MLP.
// -----------------------------------------------------------------------------

#define MAX_NODES (1 << 17)   // 131072 >= N=100000
#define MAX_TT    1024        // >= T*T = 625
#define MAX_G     1024        // >= n_graphs = 512
#define TILE_CHUNKS 512       // 512 chunks * 4 edges = 2048 edges per tile

__device__ float4       g_nodes[MAX_NODES];  // xyz + type-as-float
__device__ unsigned int g_tile_ctr;          // dynamic tile counter (reset per launch)

// ---- prep: pack (pos, atom_type) into one float4 per node -------------------
__global__ void pack_nodes_kernel(const float* __restrict__ pos,
                                  const int* __restrict__ types,
                                  int N) {
    int i = blockIdx.x * blockDim.x + threadIdx.x;
    if (i < N) {
        float4 v;
        v.x = pos[3 * i + 0];
        v.y = pos[3 * i + 1];
        v.z = pos[3 * i + 2];
        v.w = (float)types[i];
        g_nodes[i] = v;
    }
}

// ---- per-edge energy from two gathered node records --------------------------
__device__ __forceinline__ float pair_V(float4 n0, float4 n1,
                                        const float4* __restrict__ s_kk,
                                        const float* __restrict__ s_v0,
                                        int T) {
    float dx = n0.x - n1.x;
    float dy = n0.y - n1.y;
    float dz = n0.z - n1.z;
    float x2 = fmaf(dx, dx, fmaf(dy, dy, dz * dz));
    float x  = sqrtf(x2);
    int idx = (int)n0.w * T + (int)n1.w;
    float4 k = s_kk[idx];
    float  v = s_v0[idx];
    // v0 + x*(k1 + x*(k2 + x*(k3 + x*k4)))
    return fmaf(x, fmaf(x, fmaf(x, fmaf(x, k.w, k.z), k.y), k.x), v);
}

// ---- main kernel -------------------------------------------------------------
__global__ void __launch_bounds__(256)
poly_main_kernel(const int* __restrict__ map0,
                 const int* __restrict__ map1,
                 const int* __restrict__ batch,
                 const float* __restrict__ ks,
                 const float* __restrict__ v0g,
                 float* __restrict__ y,
                 long long C,        // number of 4-edge chunks
                 long long E,        // total edges (tail handled by block 0)
                 int T, int degs, int G,
                 int numTiles) {
    __shared__ float4   s_kk[MAX_TT];
    __shared__ float    s_v0[MAX_TT];
    __shared__ float    s_y[MAX_G];
    __shared__ unsigned s_tile;

    const int TT = T * T;
    for (int i = threadIdx.x; i < TT; i += blockDim.x) {
        float4 k;
        k.x = ks[i];
        k.y = (degs > 1) ? ks[TT + i]     : 0.f;
        k.z = (degs > 2) ? ks[2 * TT + i] : 0.f;
        k.w = (degs > 3) ? ks[3 * TT + i] : 0.f;
        s_kk[i] = k;
        s_v0[i] = v0g[i];
    }
    for (int i = threadIdx.x; i < G; i += blockDim.x) s_y[i] = 0.f;
    __syncthreads();

    const int4* __restrict__ m0v = (const int4*)map0;
    const int4* __restrict__ m1v = (const int4*)map1;
    const int4* __restrict__ bv  = (const int4*)batch;

    // per-thread running segment accumulator (batches are sorted -> flushes rare)
    int   cur_b = -1;
    float acc   = 0.f;

    for (;;) {
        if (threadIdx.x == 0) s_tile = atomicAdd(&g_tile_ctr, 1u);
        __syncthreads();
        unsigned t = s_tile;
        if (t >= (unsigned)numTiles) break;   // uniform across block

        long long base = (long long)t * TILE_CHUNKS;

        #pragma unroll
        for (int k = 0; k < TILE_CHUNKS / 256; ++k) {
            long long c = base + (long long)k * 256 + threadIdx.x;
            if (c < C) {
                int4 ma = m0v[c];
                int4 mb = m1v[c];
                int4 bb = bv[c];
                // batch all 8 gathers for max MLP before any dependent compute
                float4 n0 = g_nodes[ma.x];
                float4 n1 = g_nodes[mb.x];
                float4 n2 = g_nodes[ma.y];
                float4 n3 = g_nodes[mb.y];
                float4 n4 = g_nodes[ma.z];
                float4 n5 = g_nodes[mb.z];
                float4 n6 = g_nodes[ma.w];
                float4 n7 = g_nodes[mb.w];

                float V0 = pair_V(n0, n1, s_kk, s_v0, T);
                float V1 = pair_V(n2, n3, s_kk, s_v0, T);
                float V2 = pair_V(n4, n5, s_kk, s_v0, T);
                float V3 = pair_V(n6, n7, s_kk, s_v0, T);

                // register accumulation; flush only on segment change
                #pragma unroll
                for (int j = 0; j < 4; ++j) {
                    int   b = (j == 0) ? bb.x : (j == 1) ? bb.y : (j == 2) ? bb.z : bb.w;
                    float V = (j == 0) ? V0   : (j == 1) ? V1   : (j == 2) ? V2   : V3;
                    if (b == cur_b) {
                        acc += V;
                    } else {
                        if (cur_b >= 0) atomicAdd(&s_y[cur_b], acc);
                        cur_b = b;
                        acc   = V;
                    }
                }
            }
        }
        __syncthreads();   // all threads consumed s_tile before next overwrite
    }

    // flush per-thread accumulator
    if (cur_b >= 0) atomicAdd(&s_y[cur_b], acc);

    // trailing edges (E not divisible by 4): block 0 only
    if (blockIdx.x == 0 && threadIdx.x == 0) {
        for (long long e = C * 4; e < E; ++e) {
            float4 a = g_nodes[map0[e]];
            float4 b = g_nodes[map1[e]];
            float V = pair_V(a, b, s_kk, s_v0, T);
            atomicAdd(&s_y[batch[e]], V);
        }
    }

    __syncthreads();
    for (int i = threadIdx.x; i < G; i += blockDim.x) {
        float v = s_y[i];
        if (v != 0.f) atomicAdd(&y[i], v);
    }
}

// ---- launch ------------------------------------------------------------------
extern "C" void kernel_launch(void* const* d_in, const int* in_sizes, int n_in,
                              void* d_out, int out_size) {
    const float* pos     = (const float*)d_in[0];  // (N,3)  f32
    const float* ks      = (const float*)d_in[1];  // (DEGS,T,T) f32
    const float* v0      = (const float*)d_in[2];  // (T,T) f32
    const int*   mapping = (const int*)d_in[3];    // (2,E) int32
    const int*   types   = (const int*)d_in[4];    // (N,)  int32
    const int*   mbatch  = (const int*)d_in[5];    // (E,)  int32, sorted
    float* y = (float*)d_out;                      // (G,)  f32

    const int N  = in_sizes[0] / 3;
    const int TT = in_sizes[2];           // T*T
    int T = 1;
    while ((T + 1) * (T + 1) <= TT) ++T;  // integer sqrt
    const int degs = in_sizes[1] / TT;
    const long long E = (long long)in_sizes[5];
    const int G = out_size;

    const int* map0 = mapping;
    const int* map1 = mapping + E;
    const long long C = E >> 2;           // 4 edges per chunk
    const int numTiles = (int)((C + TILE_CHUNKS - 1) / TILE_CHUNKS);

    // reset dynamic tile counter + zero output (both graph-capturable)
    void* ctr_ptr = nullptr;
    cudaGetSymbolAddress(&ctr_ptr, g_tile_ctr);
    cudaMemsetAsync(ctr_ptr, 0, sizeof(unsigned int), 0);
    cudaMemsetAsync(d_out, 0, (size_t)out_size * sizeof(float), 0);

    int prep_blocks = (N + 255) / 256;
    pack_nodes_kernel<<<prep_blocks, 256>>>(pos, types, N);

    int blocks = 148 * 8;   // oversubscribed; dynamic tiles absorb occupancy limits
    poly_main_kernel<<<blocks, 256>>>(map0, map1, mbatch, ks, v0, y,
                                      C, E, T, degs, G, numTiles);
}

// round 10
// speedup vs baseline: 1.3681x; 1.3681x over previous
#include <cuda_runtime.h>
#include <stdint.h>

// -----------------------------------------------------------------------------
// Polynomial edge-energy + segment sum. (indices are int32)
//   per edge e: x = |pos[m0]-pos[m1]|, V = v0[t0,t1] + sum_p ks[p,t0,t1]*x^(p+1)
//   y[g] = segment sum over sorted mapping_batch
// R10: R5 structure (warp-shuffle reduction, 4 edges/thread, 8 batched gathers)
//      + fine-grained grid-stride (kills static-partition CTA-spread tail)
//      + exact single-wave launch (148*7 blocks @ 34 regs)
//      + type stored as int bit-pattern (no F2I in hot loop)
// -----------------------------------------------------------------------------

#define MAX_NODES (1 << 17)   // 131072 >= N=100000
#define MAX_TT    1024        // >= T*T = 625
#define MAX_G     1024        // >= n_graphs = 512

__device__ float4 g_nodes[MAX_NODES];   // xyz + type-bits-as-float

// ---- prep: pack (pos, atom_type) into one float4 per node -------------------
__global__ void pack_nodes_kernel(const float* __restrict__ pos,
                                  const int* __restrict__ types,
                                  int N) {
    int i = blockIdx.x * blockDim.x + threadIdx.x;
    if (i < N) {
        float4 v;
        v.x = pos[3 * i + 0];
        v.y = pos[3 * i + 1];
        v.z = pos[3 * i + 2];
        v.w = __int_as_float(types[i]);   // reinterpret: free to decode
        g_nodes[i] = v;
    }
}

// ---- per-edge energy from two gathered node records --------------------------
__device__ __forceinline__ float pair_V(float4 n0, float4 n1,
                                        const float4* __restrict__ s_kk,
                                        const float* __restrict__ s_v0,
                                        int T) {
    float dx = n0.x - n1.x;
    float dy = n0.y - n1.y;
    float dz = n0.z - n1.z;
    float x2 = fmaf(dx, dx, fmaf(dy, dy, dz * dz));
    float x  = sqrtf(x2);
    int idx = __float_as_int(n0.w) * T + __float_as_int(n1.w);
    float4 k = s_kk[idx];
    float  v = s_v0[idx];
    // v0 + x*(k1 + x*(k2 + x*(k3 + x*k4)))
    return fmaf(x, fmaf(x, fmaf(x, fmaf(x, k.w, k.z), k.y), k.x), v);
}

// ---- main kernel -------------------------------------------------------------
__global__ void __launch_bounds__(256)
poly_main_kernel(const int* __restrict__ map0,
                 const int* __restrict__ map1,
                 const int* __restrict__ batch,
                 const float* __restrict__ ks,
                 const float* __restrict__ v0g,
                 float* __restrict__ y,
                 long long C,        // number of 4-edge chunks
                 long long E,        // total edges (tail handled by block 0)
                 int T, int degs, int G) {
    __shared__ float4 s_kk[MAX_TT];
    __shared__ float  s_v0[MAX_TT];
    __shared__ float  s_y[MAX_G];

    const int TT = T * T;
    for (int i = threadIdx.x; i < TT; i += blockDim.x) {
        float4 k;
        k.x = ks[i];
        k.y = (degs > 1) ? ks[TT + i]     : 0.f;
        k.z = (degs > 2) ? ks[2 * TT + i] : 0.f;
        k.w = (degs > 3) ? ks[3 * TT + i] : 0.f;
        s_kk[i] = k;
        s_v0[i] = v0g[i];
    }
    for (int i = threadIdx.x; i < G; i += blockDim.x) s_y[i] = 0.f;
    __syncthreads();

    const int4* __restrict__ m0v = (const int4*)map0;
    const int4* __restrict__ m1v = (const int4*)map1;
    const int4* __restrict__ bv  = (const int4*)batch;

    const long long stride = (long long)gridDim.x * blockDim.x;
    const int lane = threadIdx.x & 31;

    // fine-grained grid-stride: all CTAs interleave over the whole range,
    // finishing within one iteration of each other (no partition tail).
    for (long long c = (long long)blockIdx.x * blockDim.x + threadIdx.x;
         c < C; c += stride) {
        int4 ma = m0v[c];
        int4 mb = m1v[c];
        int4 bb = bv[c];
        // batch all 8 gathers for max MLP before any dependent compute
        float4 n0 = g_nodes[ma.x];
        float4 n1 = g_nodes[mb.x];
        float4 n2 = g_nodes[ma.y];
        float4 n3 = g_nodes[mb.y];
        float4 n4 = g_nodes[ma.z];
        float4 n5 = g_nodes[mb.z];
        float4 n6 = g_nodes[ma.w];
        float4 n7 = g_nodes[mb.w];

        float V0 = pair_V(n0, n1, s_kk, s_v0, T);
        float V1 = pair_V(n2, n3, s_kk, s_v0, T);
        float V2 = pair_V(n4, n5, s_kk, s_v0, T);
        float V3 = pair_V(n6, n7, s_kk, s_v0, T);

        // warp-uniform segment fast path (sorted batches -> ~98% taken)
        int bl = __shfl_sync(0xffffffffu, bb.x, 0);
        bool uni = (bb.x == bl) && (bb.y == bl) && (bb.z == bl) && (bb.w == bl);
        if (__ballot_sync(0xffffffffu, uni) == 0xffffffffu) {
            float s = (V0 + V1) + (V2 + V3);
            #pragma unroll
            for (int o = 16; o > 0; o >>= 1)
                s += __shfl_xor_sync(0xffffffffu, s, o);
            if (lane == 0) atomicAdd(&s_y[bl], s);
        } else {
            atomicAdd(&s_y[bb.x], V0);
            atomicAdd(&s_y[bb.y], V1);
            atomicAdd(&s_y[bb.z], V2);
            atomicAdd(&s_y[bb.w], V3);
        }
    }

    // trailing edges (E not divisible by 4): block 0 only
    if (blockIdx.x == 0 && threadIdx.x == 0) {
        for (long long e = C * 4; e < E; ++e) {
            float4 a = g_nodes[map0[e]];
            float4 b = g_nodes[map1[e]];
            float V = pair_V(a, b, s_kk, s_v0, T);
            atomicAdd(&s_y[batch[e]], V);
        }
    }

    __syncthreads();
    // each block touches only ~#iters segments -> zero-guard keeps this cheap
    for (int i = threadIdx.x; i < G; i += blockDim.x) {
        float v = s_y[i];
        if (v != 0.f) atomicAdd(&y[i], v);
    }
}

// ---- launch ------------------------------------------------------------------
extern "C" void kernel_launch(void* const* d_in, const int* in_sizes, int n_in,
                              void* d_out, int out_size) {
    const float* pos     = (const float*)d_in[0];  // (N,3)  f32
    const float* ks      = (const float*)d_in[1];  // (DEGS,T,T) f32
    const float* v0      = (const float*)d_in[2];  // (T,T) f32
    const int*   mapping = (const int*)d_in[3];    // (2,E) int32
    const int*   types   = (const int*)d_in[4];    // (N,)  int32
    const int*   mbatch  = (const int*)d_in[5];    // (E,)  int32, sorted
    float* y = (float*)d_out;                      // (G,)  f32

    const int N  = in_sizes[0] / 3;
    const int TT = in_sizes[2];           // T*T
    int T = 1;
    while ((T + 1) * (T + 1) <= TT) ++T;  // integer sqrt
    const int degs = in_sizes[1] / TT;
    const long long E = (long long)in_sizes[5];
    const int G = out_size;

    const int* map0 = mapping;
    const int* map1 = mapping + E;
    const long long C = E >> 2;           // 4 edges per chunk

    cudaMemsetAsync(d_out, 0, (size_t)out_size * sizeof(float), 0);

    int prep_blocks = (N + 255) / 256;
    pack_nodes_kernel<<<prep_blocks, 256>>>(pos, types, N);

    // exactly one wave: 7 CTAs/SM at ~34 regs x 256 threads, 148 SMs
    int blocks = 148 * 7;
    poly_main_kernel<<<blocks, 256>>>(map0, map1, mbatch, ks, v0, y,
                                      C, E, T, degs, G);
}